// round 14
// baseline (speedup 1.0000x reference)
#include <cuda_runtime.h>
#include <cuda_bf16.h>
#include <math.h>

#define S_LEN  1024
#define B_SIZE 512
#define NTAG   48
#define PF     4
#define NCHUNK 64
#define CHUNK  (S_LEN / NCHUNK)

__device__ float g_den[B_SIZE];
__device__ float g_pnum[NCHUNK][B_SIZE];
__device__ int   g_pcnt[NCHUNK][B_SIZE];

// ---- forward kernel: one WARP per chain, 512 chains, bf16x2 math.
// Lane l (<24) owns outputs (2l, 2l+1). E in 48 bf16x2 regs (no spill).
// State: 48 duplicated bf16x2 in shared ({v,v} per tag), double buffered.
// Per chain-step LSU ops: 12 LDS.128 + 1 STS.64 (+1 LDG.64 prefetch).
__global__ void __launch_bounds__(32)
crf_fwd_kernel(const float* __restrict__ emissions,
               const int* __restrict__ mask,
               const float* __restrict__ start_t,
               const float* __restrict__ end_t,
               const float* __restrict__ trans)
{
    const int b   = blockIdx.x;
    const int l   = threadIdx.x;
    const int j0  = 2 * l;
    const int j1  = 2 * l + 1;
    const bool act = (l < NTAG / 2);    // l < 24

    __shared__ __align__(16) unsigned v_sh[2][NTAG];   // bf16x2 {v,v} per tag

    // E2[k] = bf16x2( exp(T[k][j0]), exp(T[k][j1]) )
    __nv_bfloat162 E2[NTAG];
#pragma unroll
    for (int k = 0; k < NTAG; k++) {
        float e0 = act ? __expf(trans[k * NTAG + j0]) : 0.f;
        float e1 = act ? __expf(trans[k * NTAG + j1]) : 0.f;
        E2[k] = __floats2bfloat162_rn(e0, e1);
    }

    // ---- t = 0 ----
    __nv_bfloat162 w;   // {w_j0, w_j1}
    {
        float2 em = act ? *(const float2*)(emissions + (size_t)b * NTAG + j0)
                        : make_float2(0.f, 0.f);
        float w0 = act ? __expf(start_t[j0] + em.x) : 0.f;
        float w1 = act ? __expf(start_t[act ? j1 : 0] + em.y) : 0.f;
        w = __floats2bfloat162_rn(w0, w1);
        if (act) {
            __nv_bfloat162 d0 = __bfloat162bfloat162(__low2bfloat16(w));
            __nv_bfloat162 d1 = __bfloat162bfloat162(__high2bfloat16(w));
            uint2 st; st.x = *(unsigned*)&d0; st.y = *(unsigned*)&d1;
            *(uint2*)(&v_sh[0][j0]) = st;
        }
    }

    float2 pf[PF];
#pragma unroll
    for (int k = 0; k < PF; k++) {
        int t = 1 + k;
        pf[t & (PF - 1)] = act ? *(const float2*)(emissions + ((size_t)t * B_SIZE + b) * NTAG + j0)
                               : make_float2(0.f, 0.f);
    }
    unsigned mbits;
    {
        int mt = mask[(size_t)l * B_SIZE + b];
        mbits = __ballot_sync(0xffffffffu, mt != 0);
    }
    float M = 0.f;
    int nupd = 0;
    int cur = 0;
    __syncwarp();

    for (int t = 1; t < S_LEN; t++) {
        if ((t & 31) == 0) {
            int mt = mask[(size_t)(t + l) * B_SIZE + b];
            mbits = __ballot_sync(0xffffffffu, mt != 0);
        }
        const int m_t = (mbits >> (t & 31)) & 1;

        const int slot = t & (PF - 1);
        const float e0 = __expf(pf[slot].x);
        const float e1 = __expf(pf[slot].y);
        int tn = t + PF; if (tn >= S_LEN) tn = S_LEN - 1;
        pf[slot] = act ? *(const float2*)(emissions + ((size_t)tn * B_SIZE + b) * NTAG + j0)
                       : make_float2(0.f, 0.f);
        const __nv_bfloat162 eh = __floats2bfloat162_rn(e0, e1);

        // packed matvec: acc = sum_k {v_k,v_k} * {E[k][j0],E[k][j1]}
        const uint4* vp = (const uint4*)v_sh[cur];
        __nv_bfloat162 a0 = __float2bfloat162_rn(0.f);
        __nv_bfloat162 a1 = a0, a2 = a0, a3 = a0;
#pragma unroll
        for (int q = 0; q < NTAG / 4; q++) {
            const uint4 v4 = vp[q];
            a0 = __hfma2(*(const __nv_bfloat162*)&v4.x, E2[4 * q + 0], a0);
            a1 = __hfma2(*(const __nv_bfloat162*)&v4.y, E2[4 * q + 1], a1);
            a2 = __hfma2(*(const __nv_bfloat162*)&v4.z, E2[4 * q + 2], a2);
            a3 = __hfma2(*(const __nv_bfloat162*)&v4.w, E2[4 * q + 3], a3);
        }
        __nv_bfloat162 nw = __hmul2(__hadd2(__hadd2(a0, a1), __hadd2(a2, a3)), eh);

        if (m_t) {
            w = nw;
            if (((++nupd) & 7) == 0) {
                float w0f = __low2float(w), w1f = __high2float(w);
                float r = fmaxf(w0f, w1f);
#pragma unroll
                for (int o = 16; o > 0; o >>= 1)
                    r = fmaxf(r, __shfl_xor_sync(0xffffffffu, r, o));
                r = fmaxf(r, 1e-30f);
                M += __logf(r);
                float inv = 1.f / r;
                w = __hmul2(w, __float2bfloat162_rn(inv));
            }
        }
        if (act) {
            __nv_bfloat162 d0 = __bfloat162bfloat162(__low2bfloat16(w));
            __nv_bfloat162 d1 = __bfloat162bfloat162(__high2bfloat16(w));
            uint2 st; st.x = *(unsigned*)&d0; st.y = *(unsigned*)&d1;
            *(uint2*)(&v_sh[cur ^ 1][j0]) = st;
        }
        __syncwarp();
        cur ^= 1;
    }

    // ---- finalize: denominator = M + log( sum_j w_j * exp(end_j) ) ----
    float w0f = __low2float(w), w1f = __high2float(w);
    float ee0 = act ? __expf(end_t[j0]) : 0.f;
    float ee1 = act ? __expf(end_t[act ? j1 : 0]) : 0.f;
    float c = w0f * ee0 + w1f * ee1;
#pragma unroll
    for (int o = 16; o > 0; o >>= 1)
        c += __shfl_xor_sync(0xffffffffu, c, o);
    if (l == 0) g_den[b] = M + __logf(c);
}

// ---- numerator partials: coalesced over batch, 64-way parallel over t ----
__global__ void __launch_bounds__(B_SIZE)
crf_num_kernel(const float* __restrict__ emissions,
               const int* __restrict__ tags,
               const int* __restrict__ mask,
               const float* __restrict__ start_t,
               const float* __restrict__ trans)
{
    const int b  = threadIdx.x;
    const int c  = blockIdx.x;
    const int t0 = c * CHUNK;

    float acc = 0.f;
    int cnt = 0;
    int tp = (t0 > 0) ? tags[(t0 - 1) * B_SIZE + b] : 0;
#pragma unroll
    for (int k = 0; k < CHUNK; k++) {
        int t  = t0 + k;
        int tg = tags[t * B_SIZE + b];
        int m  = mask[t * B_SIZE + b];
        cnt += m;
        if (t == 0) {
            acc += start_t[tg] + emissions[(size_t)b * NTAG + tg];
        } else {
            acc += (trans[tp * NTAG + tg] +
                    emissions[((size_t)t * B_SIZE + b) * NTAG + tg]) * (float)m;
        }
        tp = tg;
    }
    g_pnum[c][b] = acc;
    g_pcnt[c][b] = cnt;
}

// ---- final: end-term + mean(num - den) ----
__global__ void __launch_bounds__(B_SIZE)
crf_reduce_kernel(float* __restrict__ out,
                  const int* __restrict__ tags,
                  const float* __restrict__ end_t)
{
    __shared__ float sh[B_SIZE];
    const int b = threadIdx.x;

    float num = 0.f;
    int cnt = 0;
#pragma unroll
    for (int c = 0; c < NCHUNK; c++) { num += g_pnum[c][b]; cnt += g_pcnt[c][b]; }
    num += end_t[tags[(cnt - 1) * B_SIZE + b]];

    sh[b] = num - g_den[b];
    __syncthreads();
#pragma unroll
    for (int o = B_SIZE / 2; o > 0; o >>= 1) {
        if (b < o) sh[b] += sh[b + o];
        __syncthreads();
    }
    if (b == 0) out[0] = sh[0] * (1.f / (float)B_SIZE);
}

extern "C" void kernel_launch(void* const* d_in, const int* in_sizes, int n_in,
                              void* d_out, int out_size)
{
    const float* emissions = (const float*)d_in[0];
    const int*   tags      = (const int*)d_in[1];
    const int*   mask      = (const int*)d_in[2];
    const float* start_t   = (const float*)d_in[3];
    const float* end_t     = (const float*)d_in[4];
    const float* trans     = (const float*)d_in[5];

    crf_fwd_kernel<<<B_SIZE, 32>>>(emissions, mask, start_t, end_t, trans);
    crf_num_kernel<<<NCHUNK, B_SIZE>>>(emissions, tags, mask, start_t, trans);
    crf_reduce_kernel<<<1, B_SIZE>>>((float*)d_out, tags, end_t);
}

// round 15
// speedup vs baseline: 1.1117x; 1.1117x over previous
#include <cuda_runtime.h>
#include <cuda_bf16.h>
#include <math.h>

#define S_LEN  1024
#define B_SIZE 512
#define NTAG   48
#define PF     4
#define NCHUNK 64
#define CHUNK  (S_LEN / NCHUNK)

__device__ float g_den[B_SIZE];
__device__ float g_pnum[NCHUNK][B_SIZE];
__device__ int   g_pcnt[NCHUNK][B_SIZE];

// ---- forward kernel: R6 shape (512 CTAs x 64 threads, 2 warps/chain),
// but state broadcast in bf16: 6 LDS.128 + 24 HFMA2 per thread-step.
__global__ void __launch_bounds__(64)
crf_fwd_kernel(const float* __restrict__ emissions,
               const int* __restrict__ mask,
               const float* __restrict__ start_t,
               const float* __restrict__ end_t,
               const float* __restrict__ trans)
{
    const int b    = blockIdx.x;
    const int j    = threadIdx.x;        // 0..63, tags 0..47
    const int lane = j & 31;
    const int wid  = j >> 5;
    const bool act = (j < NTAG);
    const int jc   = act ? j : 0;        // clamped index for safe loads

    __shared__ __align__(16) __nv_bfloat16 v_sh[2][64];  // 48 used, bf16
    __shared__ float wred[2];

    // E2[p] = bf16x2( exp(T[2p][j]), exp(T[2p+1][j]) ), p = 0..23
    __nv_bfloat162 E2[NTAG / 2];
#pragma unroll
    for (int p = 0; p < NTAG / 2; p++) {
        float e0 = act ? __expf(trans[(2 * p) * NTAG + j]) : 0.f;
        float e1 = act ? __expf(trans[(2 * p + 1) * NTAG + j]) : 0.f;
        E2[p] = __floats2bfloat162_rn(e0, e1);
    }

    // ---- t = 0 ----
    float w;
    {
        float em0 = emissions[(size_t)b * NTAG + jc];
        w = act ? __expf(start_t[jc] + em0) : 0.f;
        v_sh[0][j] = __float2bfloat16(w);      // j>=48 writes harmless pad
        v_sh[1][j] = __float2bfloat16(0.f);
    }

    float pf[PF];
#pragma unroll
    for (int k = 0; k < PF; k++) {
        int t = 1 + k;
        pf[t & (PF - 1)] = emissions[((size_t)t * B_SIZE + b) * NTAG + jc];
    }
    unsigned mbits;
    {
        int mt = mask[(size_t)lane * B_SIZE + b];
        mbits = __ballot_sync(0xffffffffu, mt != 0);
    }
    float M = 0.f;
    int nupd = 0;
    int cur = 0;
    __syncthreads();

    for (int t = 1; t < S_LEN; t++) {
        if ((t & 31) == 0) {
            int mt = mask[(size_t)(t + lane) * B_SIZE + b];
            mbits = __ballot_sync(0xffffffffu, mt != 0);
        }
        const int m_t = (mbits >> (t & 31)) & 1;

        const int slot = t & (PF - 1);
        const float e_em = __expf(pf[slot]);
        int tn = t + PF; if (tn >= S_LEN) tn = S_LEN - 1;
        pf[slot] = emissions[((size_t)tn * B_SIZE + b) * NTAG + jc];

        // bf16 matvec: 6 broadcast LDS.128 (48 bf16), 24 HFMA2
        const uint4* vp = (const uint4*)v_sh[cur];
        __nv_bfloat162 a0 = __float2bfloat162_rn(0.f);
        __nv_bfloat162 a1 = a0, a2 = a0, a3 = a0;
#pragma unroll
        for (int q = 0; q < 6; q++) {
            const uint4 v4 = vp[q];
            a0 = __hfma2(*(const __nv_bfloat162*)&v4.x, E2[4 * q + 0], a0);
            a1 = __hfma2(*(const __nv_bfloat162*)&v4.y, E2[4 * q + 1], a1);
            a2 = __hfma2(*(const __nv_bfloat162*)&v4.z, E2[4 * q + 2], a2);
            a3 = __hfma2(*(const __nv_bfloat162*)&v4.w, E2[4 * q + 3], a3);
        }
        const __nv_bfloat162 s2 = __hadd2(__hadd2(a0, a1), __hadd2(a2, a3));
        const float nw = (__low2float(s2) + __high2float(s2)) * e_em;

        if (m_t) {                 // uniform across block
            w = nw;
            if (((++nupd) & 7) == 0) {
                float r = w;
#pragma unroll
                for (int o = 16; o > 0; o >>= 1)
                    r = fmaxf(r, __shfl_xor_sync(0xffffffffu, r, o));
                if (lane == 0) wred[wid] = r;
                __syncthreads();
                r = fmaxf(fmaxf(wred[0], wred[1]), 1e-30f);
                M += __logf(r);
                w *= (1.f / r);
            }
        }
        v_sh[cur ^ 1][j] = __float2bfloat16(w);   // pad lanes write 0
        __syncthreads();
        cur ^= 1;
    }

    // ---- finalize denominator ----
    float ee = act ? __expf(end_t[jc]) : 0.f;
    float c = w * ee;
#pragma unroll
    for (int o = 16; o > 0; o >>= 1)
        c += __shfl_xor_sync(0xffffffffu, c, o);
    if (lane == 0) wred[wid] = c;
    __syncthreads();
    if (j == 0) g_den[b] = M + __logf(wred[0] + wred[1]);
}

// ---- numerator partials: coalesced over batch, 64-way parallel over t ----
__global__ void __launch_bounds__(B_SIZE)
crf_num_kernel(const float* __restrict__ emissions,
               const int* __restrict__ tags,
               const int* __restrict__ mask,
               const float* __restrict__ start_t,
               const float* __restrict__ trans)
{
    const int b  = threadIdx.x;
    const int c  = blockIdx.x;
    const int t0 = c * CHUNK;

    float acc = 0.f;
    int cnt = 0;
    int tp = (t0 > 0) ? tags[(t0 - 1) * B_SIZE + b] : 0;
#pragma unroll
    for (int k = 0; k < CHUNK; k++) {
        int t  = t0 + k;
        int tg = tags[t * B_SIZE + b];
        int m  = mask[t * B_SIZE + b];
        cnt += m;
        if (t == 0) {
            acc += start_t[tg] + emissions[(size_t)b * NTAG + tg];
        } else {
            acc += (trans[tp * NTAG + tg] +
                    emissions[((size_t)t * B_SIZE + b) * NTAG + tg]) * (float)m;
        }
        tp = tg;
    }
    g_pnum[c][b] = acc;
    g_pcnt[c][b] = cnt;
}

// ---- final: end-term + mean(num - den) ----
__global__ void __launch_bounds__(B_SIZE)
crf_reduce_kernel(float* __restrict__ out,
                  const int* __restrict__ tags,
                  const float* __restrict__ end_t)
{
    __shared__ float sh[B_SIZE];
    const int b = threadIdx.x;

    float num = 0.f;
    int cnt = 0;
#pragma unroll
    for (int c = 0; c < NCHUNK; c++) { num += g_pnum[c][b]; cnt += g_pcnt[c][b]; }
    num += end_t[tags[(cnt - 1) * B_SIZE + b]];

    sh[b] = num - g_den[b];
    __syncthreads();
#pragma unroll
    for (int o = B_SIZE / 2; o > 0; o >>= 1) {
        if (b < o) sh[b] += sh[b + o];
        __syncthreads();
    }
    if (b == 0) out[0] = sh[0] * (1.f / (float)B_SIZE);
}

extern "C" void kernel_launch(void* const* d_in, const int* in_sizes, int n_in,
                              void* d_out, int out_size)
{
    const float* emissions = (const float*)d_in[0];
    const int*   tags      = (const int*)d_in[1];
    const int*   mask      = (const int*)d_in[2];
    const float* start_t   = (const float*)d_in[3];
    const float* end_t     = (const float*)d_in[4];
    const float* trans     = (const float*)d_in[5];

    crf_fwd_kernel<<<B_SIZE, 64>>>(emissions, mask, start_t, end_t, trans);
    crf_num_kernel<<<NCHUNK, B_SIZE>>>(emissions, tags, mask, start_t, trans);
    crf_reduce_kernel<<<1, B_SIZE>>>((float*)d_out, tags, end_t);
}